// round 13
// baseline (speedup 1.0000x reference)
#include <cuda_runtime.h>

#define STEPS   2048
#define CHUNK   32      // steps buffered in smem before a coalesced drain
#define SUB     4       // steps buffered in registers before one STS burst
#define TPB     32      // ONE warp per block -> near-perfect SM load balance
#define STRIDE  100     // floats per lane-row in smem (96 data + 4 pad; 100%32=4
                        //  => conflict-free 8-lane STS.128 wavefronts)
#define HSTEP   0.01f
#define NPQ     (CHUNK * 3 / 4)   // 24 float4 per row per chunk

typedef unsigned long long u64;

__device__ __forceinline__ u64 pack2(float lo, float hi) {
    u64 r;
    asm("mov.b64 %0, {%1, %2};" : "=l"(r) : "f"(lo), "f"(hi));
    return r;
}
__device__ __forceinline__ void unpack2(u64 v, float& lo, float& hi) {
    asm("mov.b64 {%0, %1}, %2;" : "=f"(lo), "=f"(hi) : "l"(v));
}
__device__ __forceinline__ u64 fma2(u64 a, u64 b, u64 c) {
    u64 d;
    asm("fma.rn.f32x2 %0, %1, %2, %3;" : "=l"(d) : "l"(a), "l"(b), "l"(c));
    return d;
}
__device__ __forceinline__ float rcp_fast(float x) {
    float r;
    asm("rcp.approx.f32 %0, %1;" : "=f"(r) : "f"(x));
    return r;
}

__global__ __launch_bounds__(TPB) void ode_rnn_kernel(
    const float* __restrict__ x, const float* __restrict__ kern,
    float* __restrict__ out)
{
    __shared__ float sb[32 * STRIDE];

    const int lane = threadIdx.x & 31;
    const int row  = blockIdx.x * 32 + lane;

    // kernel coefficients: K0 = kern[0:8], KA = kern[8:16]
    // rate order: Kut,Ktd,Ksd,Kus,Ktu,Kdt,Kds,Ksu = idx 0..7
    float k0[8], ka[8];
#pragma unroll
    for (int i = 0; i < 8; ++i) {
        k0[i] = __ldg(kern + i);
        ka[i] = __ldg(kern + 8 + i);
    }

    // Expand U = 3.4 - T - D - S; y_i affine in (T,D,S) with K = K0 + fr*KA
    // -> X_i = d0'_i + fr*dA'_i (H pre-scaled, identity folded).
    float c0p[3], c0T[3], c0D[3], c0S[3];
    float cAp[3], cAT[3], cAD[3], cAS[3];

    c0p[0] = 3.4f * k0[0];  cAp[0] = 3.4f * ka[0];
    c0T[0] = -(k0[0] + k0[4] + k0[1]);  cAT[0] = -(ka[0] + ka[4] + ka[1]);
    c0D[0] = k0[5] - k0[0];             cAD[0] = ka[5] - ka[0];
    c0S[0] = -k0[0];                    cAS[0] = -ka[0];

    c0p[1] = 0.0f;                      cAp[1] = 0.0f;
    c0T[1] = k0[1];                     cAT[1] = ka[1];
    c0D[1] = -(k0[5] + k0[6]);          cAD[1] = -(ka[5] + ka[6]);
    c0S[1] = k0[2];                     cAS[1] = ka[2];

    c0p[2] = 3.4f * k0[3];  cAp[2] = 3.4f * ka[3];
    c0T[2] = -k0[3];                    cAT[2] = -ka[3];
    c0D[2] = k0[6] - k0[3];             cAD[2] = ka[6] - ka[3];
    c0S[2] = -(k0[3] + k0[7] + k0[2]);  cAS[2] = -(ka[3] + ka[7] + ka[2]);

    u64 GP[3], GT[3], GD[3], GS[3];
#pragma unroll
    for (int i = 0; i < 3; ++i) {
        GP[i] = pack2(HSTEP * c0p[i], HSTEP * cAp[i]);
        GT[i] = pack2(HSTEP * c0T[i] + (i == 0 ? 1.0f : 0.0f), HSTEP * cAT[i]);
        GD[i] = pack2(HSTEP * c0D[i] + (i == 1 ? 1.0f : 0.0f), HSTEP * cAD[i]);
        GS[i] = pack2(HSTEP * c0S[i] + (i == 2 ? 1.0f : 0.0f), HSTEP * cAS[i]);
    }

    float T = x[row * 3 + 0];
    float D = x[row * 3 + 1];
    float S = x[row * 3 + 2];

    float* outw = out + (size_t)(blockIdx.x * 32) * (STEPS * 3);

    for (int c = 0; c < STEPS / CHUNK; ++c) {
#pragma unroll
        for (int q = 0; q < CHUNK / SUB; ++q) {
            float st[SUB * 3];
#pragma unroll
            for (int t = 0; t < SUB; ++t) {
                // fr = A/(0.43+A), A = max(0, 1.3-2S).
                // 0.43+A == max(1.73-2S, 0.43) when A>0; when A==0 the
                // clamped rcp is multiplied by A==0 -> fr=0 exactly.
                // This runs the RCP in parallel with the A max, cutting
                // the serial chain from ~40 to ~32 cyc/step.
                float den = fmaxf(fmaf(-2.0f, S, 1.73f), 0.43f);
                float r   = rcp_fast(den);
                float A   = fmaxf(0.0f, fmaf(-2.0f, S, 1.3f));
                float fr  = A * r;

                u64 TT = pack2(T, T);
                u64 DD = pack2(D, D);
                u64 SS = pack2(S, S);

                u64 d0 = fma2(TT, GT[0], GP[0]);
                u64 d1 = fma2(TT, GT[1], GP[1]);
                u64 d2 = fma2(TT, GT[2], GP[2]);
                d0 = fma2(DD, GD[0], d0);
                d1 = fma2(DD, GD[1], d1);
                d2 = fma2(DD, GD[2], d2);
                d0 = fma2(SS, GS[0], d0);
                d1 = fma2(SS, GS[1], d1);
                d2 = fma2(SS, GS[2], d2);

                float l0, h0, l1, h1, l2, h2;
                unpack2(d0, l0, h0);
                unpack2(d1, l1, h1);
                unpack2(d2, l2, h2);
                T = fmaf(fr, h0, l0);
                D = fmaf(fr, h1, l1);
                S = fmaf(fr, h2, l2);

                st[t * 3 + 0] = T;
                st[t * 3 + 1] = D;
                st[t * 3 + 2] = S;
            }
            // 12 floats -> 3x STS.128 (stride-100 pad => conflict-free)
#pragma unroll
            for (int v = 0; v < 3; ++v) {
                *(float4*)&sb[lane * STRIDE + q * 12 + v * 4] =
                    make_float4(st[v * 4 + 0], st[v * 4 + 1],
                                st[v * 4 + 2], st[v * 4 + 3]);
            }
        }
        __syncwarp();
        // Coalesced drain: 32 rows x 96 floats = 768 float4, 24 per row
        // (384B contiguous per row in gmem). 4 batches of load-6/store-6.
#pragma unroll
        for (int h = 0; h < 4; ++h) {
            float4 v[6];
#pragma unroll
            for (int k = 0; k < 6; ++k) {
                int i  = (h * 6 + k) * 32 + lane;
                int rr = i / NPQ;
                int j  = i - rr * NPQ;
                v[k] = *(const float4*)&sb[rr * STRIDE + j * 4];
            }
#pragma unroll
            for (int k = 0; k < 6; ++k) {
                int i  = (h * 6 + k) * 32 + lane;
                int rr = i / NPQ;
                int j  = i - rr * NPQ;
                __stcs((float4*)&outw[(size_t)rr * (STEPS * 3) +
                                      c * (CHUNK * 3) + j * 4], v[k]);
            }
        }
        __syncwarp();
    }
}

extern "C" void kernel_launch(void* const* d_in, const int* in_sizes, int n_in,
                              void* d_out, int out_size) {
    const float* x    = (const float*)d_in[0];   // (32768, 3) f32
    const float* kern = (const float*)d_in[1];   // (20,)     f32
    float*       out  = (float*)d_out;           // (32768, 2048, 3) f32

    int rows   = in_sizes[0] / 3;                // 32768
    int blocks = rows / 32;                      // 1024 one-warp blocks
    ode_rnn_kernel<<<blocks, TPB>>>(x, kern, out);
}

// round 14
// speedup vs baseline: 1.0087x; 1.0087x over previous
#include <cuda_runtime.h>

#define STEPS   2048
#define CHUNK   16      // steps buffered in smem before a coalesced drain
#define SUB     4       // steps buffered in registers before one STS burst
#define TPB     32      // ONE warp per block -> near-perfect SM load balance
#define STRIDE  52      // floats per lane-row in smem (pad: conflict-free STS.128)
#define HSTEP   0.01f

typedef unsigned long long u64;

__device__ __forceinline__ u64 pack2(float lo, float hi) {
    u64 r;
    asm("mov.b64 %0, {%1, %2};" : "=l"(r) : "f"(lo), "f"(hi));
    return r;
}
__device__ __forceinline__ void unpack2(u64 v, float& lo, float& hi) {
    asm("mov.b64 {%0, %1}, %2;" : "=f"(lo), "=f"(hi) : "l"(v));
}
__device__ __forceinline__ u64 fma2(u64 a, u64 b, u64 c) {
    u64 d;
    asm("fma.rn.f32x2 %0, %1, %2, %3;" : "=l"(d) : "l"(a), "l"(b), "l"(c));
    return d;
}
__device__ __forceinline__ float rcp_fast(float x) {
    float r;
    asm("rcp.approx.f32 %0, %1;" : "=f"(r) : "f"(x));
    return r;
}

__global__ __launch_bounds__(TPB) void ode_rnn_kernel(
    const float* __restrict__ x, const float* __restrict__ kern,
    float* __restrict__ out)
{
    __shared__ float sb[32 * STRIDE];

    const int lane = threadIdx.x & 31;
    const int row  = blockIdx.x * 32 + lane;

    // kernel coefficients: K0 = kern[0:8], KA = kern[8:16]
    // rate order: Kut,Ktd,Ksd,Kus,Ktu,Kdt,Kds,Ksu = idx 0..7
    float k0[8], ka[8];
#pragma unroll
    for (int i = 0; i < 8; ++i) {
        k0[i] = __ldg(kern + i);
        ka[i] = __ldg(kern + 8 + i);
    }

    // Expand U = 3.4 - T - D - S; y_i affine in (T,D,S) with K = K0 + fr*KA
    // -> X_i = d0'_i + fr*dA'_i (H pre-scaled, identity folded).
    float c0p[3], c0T[3], c0D[3], c0S[3];
    float cAp[3], cAT[3], cAD[3], cAS[3];

    c0p[0] = 3.4f * k0[0];  cAp[0] = 3.4f * ka[0];
    c0T[0] = -(k0[0] + k0[4] + k0[1]);  cAT[0] = -(ka[0] + ka[4] + ka[1]);
    c0D[0] = k0[5] - k0[0];             cAD[0] = ka[5] - ka[0];
    c0S[0] = -k0[0];                    cAS[0] = -ka[0];

    c0p[1] = 0.0f;                      cAp[1] = 0.0f;
    c0T[1] = k0[1];                     cAT[1] = ka[1];
    c0D[1] = -(k0[5] + k0[6]);          cAD[1] = -(ka[5] + ka[6]);
    c0S[1] = k0[2];                     cAS[1] = ka[2];

    c0p[2] = 3.4f * k0[3];  cAp[2] = 3.4f * ka[3];
    c0T[2] = -k0[3];                    cAT[2] = -ka[3];
    c0D[2] = k0[6] - k0[3];             cAD[2] = ka[6] - ka[3];
    c0S[2] = -(k0[3] + k0[7] + k0[2]);  cAS[2] = -(ka[3] + ka[7] + ka[2]);

    u64 GP[3], GT[3], GD[3], GS[3];
#pragma unroll
    for (int i = 0; i < 3; ++i) {
        GP[i] = pack2(HSTEP * c0p[i], HSTEP * cAp[i]);
        GT[i] = pack2(HSTEP * c0T[i] + (i == 0 ? 1.0f : 0.0f), HSTEP * cAT[i]);
        GD[i] = pack2(HSTEP * c0D[i] + (i == 1 ? 1.0f : 0.0f), HSTEP * cAD[i]);
        GS[i] = pack2(HSTEP * c0S[i] + (i == 2 ? 1.0f : 0.0f), HSTEP * cAS[i]);
    }

    float T = x[row * 3 + 0];
    float D = x[row * 3 + 1];
    float S = x[row * 3 + 2];

    float* outw = out + (size_t)(blockIdx.x * 32) * (STEPS * 3);

    for (int c = 0; c < STEPS / CHUNK; ++c) {
#pragma unroll
        for (int q = 0; q < CHUNK / SUB; ++q) {
            float st[SUB * 3];
#pragma unroll
            for (int t = 0; t < SUB; ++t) {
                // fr = A/(0.43+A), A = max(0, 1.3-2S).
                // 0.43+A == max(1.73-2S, 0.43) whenever A>0; when A==0 the
                // clamped rcp is multiplied by A==0 -> fr=0 exactly. This
                // lets the RCP start in parallel with A's max, cutting the
                // serial chain ~40 -> ~32 cyc/step.
                float den = fmaxf(fmaf(-2.0f, S, 1.73f), 0.43f);
                float r   = rcp_fast(den);
                float A   = fmaxf(0.0f, fmaf(-2.0f, S, 1.3f));
                float fr  = A * r;

                u64 TT = pack2(T, T);
                u64 DD = pack2(D, D);
                u64 SS = pack2(S, S);

                u64 d0 = fma2(TT, GT[0], GP[0]);
                u64 d1 = fma2(TT, GT[1], GP[1]);
                u64 d2 = fma2(TT, GT[2], GP[2]);
                d0 = fma2(DD, GD[0], d0);
                d1 = fma2(DD, GD[1], d1);
                d2 = fma2(DD, GD[2], d2);
                d0 = fma2(SS, GS[0], d0);
                d1 = fma2(SS, GS[1], d1);
                d2 = fma2(SS, GS[2], d2);

                float l0, h0, l1, h1, l2, h2;
                unpack2(d0, l0, h0);
                unpack2(d1, l1, h1);
                unpack2(d2, l2, h2);
                T = fmaf(fr, h0, l0);
                D = fmaf(fr, h1, l1);
                S = fmaf(fr, h2, l2);

                st[t * 3 + 0] = T;
                st[t * 3 + 1] = D;
                st[t * 3 + 2] = S;
            }
            // 12 floats -> 3x STS.128 (stride-52 pad => conflict-free)
#pragma unroll
            for (int v = 0; v < 3; ++v) {
                *(float4*)&sb[lane * STRIDE + q * 12 + v * 4] =
                    make_float4(st[v * 4 + 0], st[v * 4 + 1],
                                st[v * 4 + 2], st[v * 4 + 3]);
            }
        }
        __syncwarp();
        // Coalesced drain: 32 rows x 48 floats = 384 float4, 12 per row.
        // Two batches of load-6-then-store-6 (deep LSU MLP, bounded regs).
#pragma unroll
        for (int h = 0; h < 2; ++h) {
            float4 v[6];
#pragma unroll
            for (int k = 0; k < 6; ++k) {
                int i  = (h * 6 + k) * 32 + lane;
                int rr = i / 12;
                int j  = i - rr * 12;
                v[k] = *(const float4*)&sb[rr * STRIDE + j * 4];
            }
#pragma unroll
            for (int k = 0; k < 6; ++k) {
                int i  = (h * 6 + k) * 32 + lane;
                int rr = i / 12;
                int j  = i - rr * 12;
                __stcs((float4*)&outw[(size_t)rr * (STEPS * 3) +
                                      c * (CHUNK * 3) + j * 4], v[k]);
            }
        }
        __syncwarp();
    }
}

extern "C" void kernel_launch(void* const* d_in, const int* in_sizes, int n_in,
                              void* d_out, int out_size) {
    const float* x    = (const float*)d_in[0];   // (32768, 3) f32
    const float* kern = (const float*)d_in[1];   // (20,)     f32
    float*       out  = (float*)d_out;           // (32768, 2048, 3) f32

    int rows   = in_sizes[0] / 3;                // 32768
    int blocks = rows / 32;                      // 1024 one-warp blocks
    ode_rnn_kernel<<<blocks, TPB>>>(x, kern, out);
}

// round 15
// speedup vs baseline: 1.0804x; 1.0710x over previous
#include <cuda_runtime.h>

#define STEPS   2048
#define CHUNK   8       // steps buffered in smem before a coalesced drain
#define SUB     4       // steps buffered in registers before one STS burst
#define TPB     32      // ONE warp per block -> near-perfect SM load balance
#define STRIDE  28      // floats per lane-row in smem (pad: conflict-free STS.128)
#define HSTEP   0.01f

typedef unsigned long long u64;

__device__ __forceinline__ u64 pack2(float lo, float hi) {
    u64 r;
    asm("mov.b64 %0, {%1, %2};" : "=l"(r) : "f"(lo), "f"(hi));
    return r;
}
__device__ __forceinline__ void unpack2(u64 v, float& lo, float& hi) {
    asm("mov.b64 {%0, %1}, %2;" : "=f"(lo), "=f"(hi) : "l"(v));
}
__device__ __forceinline__ u64 fma2(u64 a, u64 b, u64 c) {
    u64 d;
    asm("fma.rn.f32x2 %0, %1, %2, %3;" : "=l"(d) : "l"(a), "l"(b), "l"(c));
    return d;
}
__device__ __forceinline__ float rcp_fast(float x) {
    float r;
    asm("rcp.approx.f32 %0, %1;" : "=f"(r) : "f"(x));
    return r;
}

__global__ __launch_bounds__(TPB) void ode_rnn_kernel(
    const float* __restrict__ x, const float* __restrict__ kern,
    float* __restrict__ out)
{
    __shared__ float sb[32 * STRIDE];

    const int lane = threadIdx.x & 31;
    const int row  = blockIdx.x * 32 + lane;

    // kernel coefficients: K0 = kern[0:8], KA = kern[8:16]
    // rate order: Kut,Ktd,Ksd,Kus,Ktu,Kdt,Kds,Ksu = idx 0..7
    float k0[8], ka[8];
#pragma unroll
    for (int i = 0; i < 8; ++i) {
        k0[i] = __ldg(kern + i);
        ka[i] = __ldg(kern + 8 + i);
    }

    // Expand U = 3.4 - T - D - S; y_i affine in (T,D,S) with K = K0 + fr*KA
    // -> X_i = d0'_i + fr*dA'_i (H pre-scaled, identity folded).
    float c0p[3], c0T[3], c0D[3], c0S[3];
    float cAp[3], cAT[3], cAD[3], cAS[3];

    c0p[0] = 3.4f * k0[0];  cAp[0] = 3.4f * ka[0];
    c0T[0] = -(k0[0] + k0[4] + k0[1]);  cAT[0] = -(ka[0] + ka[4] + ka[1]);
    c0D[0] = k0[5] - k0[0];             cAD[0] = ka[5] - ka[0];
    c0S[0] = -k0[0];                    cAS[0] = -ka[0];

    c0p[1] = 0.0f;                      cAp[1] = 0.0f;
    c0T[1] = k0[1];                     cAT[1] = ka[1];
    c0D[1] = -(k0[5] + k0[6]);          cAD[1] = -(ka[5] + ka[6]);
    c0S[1] = k0[2];                     cAS[1] = ka[2];

    c0p[2] = 3.4f * k0[3];  cAp[2] = 3.4f * ka[3];
    c0T[2] = -k0[3];                    cAT[2] = -ka[3];
    c0D[2] = k0[6] - k0[3];             cAD[2] = ka[6] - ka[3];
    c0S[2] = -(k0[3] + k0[7] + k0[2]);  cAS[2] = -(ka[3] + ka[7] + ka[2]);

    u64 GP[3], GT[3], GD[3], GS[3];
#pragma unroll
    for (int i = 0; i < 3; ++i) {
        GP[i] = pack2(HSTEP * c0p[i], HSTEP * cAp[i]);
        GT[i] = pack2(HSTEP * c0T[i] + (i == 0 ? 1.0f : 0.0f), HSTEP * cAT[i]);
        GD[i] = pack2(HSTEP * c0D[i] + (i == 1 ? 1.0f : 0.0f), HSTEP * cAD[i]);
        GS[i] = pack2(HSTEP * c0S[i] + (i == 2 ? 1.0f : 0.0f), HSTEP * cAS[i]);
    }

    float T = x[row * 3 + 0];
    float D = x[row * 3 + 1];
    float S = x[row * 3 + 2];

    float* outw = out + (size_t)(blockIdx.x * 32) * (STEPS * 3);

    for (int c = 0; c < STEPS / CHUNK; ++c) {
#pragma unroll
        for (int q = 0; q < CHUNK / SUB; ++q) {
            float st[SUB * 3];
#pragma unroll
            for (int t = 0; t < SUB; ++t) {
                // A = max(0, 1.3 - 2*S);  fr = A/(0.43 + A)
                float A   = fmaxf(0.0f, fmaf(-2.0f, S, 1.3f));
                float den = 0.43f + A;
                float r   = rcp_fast(den);
                float fr  = A * r;

                u64 TT = pack2(T, T);
                u64 DD = pack2(D, D);
                u64 SS = pack2(S, S);

                u64 d0 = fma2(TT, GT[0], GP[0]);
                u64 d1 = fma2(TT, GT[1], GP[1]);
                u64 d2 = fma2(TT, GT[2], GP[2]);
                d0 = fma2(DD, GD[0], d0);
                d1 = fma2(DD, GD[1], d1);
                d2 = fma2(DD, GD[2], d2);
                d0 = fma2(SS, GS[0], d0);
                d1 = fma2(SS, GS[1], d1);
                d2 = fma2(SS, GS[2], d2);

                float l0, h0, l1, h1, l2, h2;
                unpack2(d0, l0, h0);
                unpack2(d1, l1, h1);
                unpack2(d2, l2, h2);
                T = fmaf(fr, h0, l0);
                D = fmaf(fr, h1, l1);
                S = fmaf(fr, h2, l2);

                st[t * 3 + 0] = T;
                st[t * 3 + 1] = D;
                st[t * 3 + 2] = S;
            }
            // 12 floats -> 3x STS.128 (stride-28 pad => conflict-free)
#pragma unroll
            for (int v = 0; v < 3; ++v) {
                *(float4*)&sb[lane * STRIDE + q * 12 + v * 4] =
                    make_float4(st[v * 4 + 0], st[v * 4 + 1],
                                st[v * 4 + 2], st[v * 4 + 3]);
            }
        }
        __syncwarp();
        // Coalesced drain: 32 rows x 24 floats = 192 float4, 6 per row.
        // All 6 loads first (deep LSU MLP), then all 6 stores back-to-back.
        {
            float4 v[6];
#pragma unroll
            for (int k = 0; k < 6; ++k) {
                int i  = k * 32 + lane;
                int rr = i / 6;
                int j  = i - rr * 6;
                v[k] = *(const float4*)&sb[rr * STRIDE + j * 4];
            }
#pragma unroll
            for (int k = 0; k < 6; ++k) {
                int i  = k * 32 + lane;
                int rr = i / 6;
                int j  = i - rr * 6;
                __stcs((float4*)&outw[(size_t)rr * (STEPS * 3) +
                                      c * (CHUNK * 3) + j * 4], v[k]);
            }
        }
        __syncwarp();
    }
}

extern "C" void kernel_launch(void* const* d_in, const int* in_sizes, int n_in,
                              void* d_out, int out_size) {
    const float* x    = (const float*)d_in[0];   // (32768, 3) f32
    const float* kern = (const float*)d_in[1];   // (20,)     f32
    float*       out  = (float*)d_out;           // (32768, 2048, 3) f32

    int rows   = in_sizes[0] / 3;                // 32768
    int blocks = rows / 32;                      // 1024 one-warp blocks
    ode_rnn_kernel<<<blocks, TPB>>>(x, kern, out);
}